// round 3
// baseline (speedup 1.0000x reference)
#include <cuda_runtime.h>

#define NB1 148           // K1 blocks (one wave of 1024-thread blocks)
#define G 128             // N_SUBJECTS * N_LABELS
#define D 128

// Scratch (no allocations allowed): ~9.8 MB
__device__ float g_part[NB1 * G * D];     // per-block partial centroid sums
__device__ int   g_cntpart[NB1 * G];      // per-block partial point counts
__device__ float g_centroid[G * D];
__device__ float g_rows[G];               // row counts (2 * point count), as float
__device__ float g_denssum[G];

// ---------------------------------------------------------------------------
// K1: per-block partial segment sums. Each warp owns 4 groups, accumulates in
// registers; membership via ballot scan of staged group ids. No fp atomics.
// ---------------------------------------------------------------------------
__global__ __launch_bounds__(1024, 1)
void k1_centroid_partials(const float4* __restrict__ X4,
                          const int* __restrict__ subj,
                          const int* __restrict__ lab,
                          int B)
{
    __shared__ int sg[1024];
    const int w    = threadIdx.x >> 5;     // warp id 0..31, owns groups [4w,4w+4)
    const int lane = threadIdx.x & 31;

    const int chunk = (B + gridDim.x - 1) / gridDim.x;
    const int c0 = blockIdx.x * chunk;
    const int c1 = min(c0 + chunk, B);

    float4 a0 = make_float4(0.f,0.f,0.f,0.f);
    float4 a1 = a0, a2 = a0, a3 = a0;
    int n0 = 0, n1 = 0, n2 = 0, n3 = 0;

    for (int t0 = c0; t0 < c1; t0 += 1024) {
        const int n = min(1024, c1 - t0);
        __syncthreads();
        if ((int)threadIdx.x < n) {
            int p = t0 + threadIdx.x;
            sg[threadIdx.x] = subj[p] * 8 + lab[p];
        }
        __syncthreads();

        for (int base = 0; base < n; base += 32) {
            const int i = base + lane;
            const int myg = (i < n) ? sg[i] : -1;
            unsigned m = __ballot_sync(0xffffffffu, (myg >> 2) == w);
            while (m) {
                const int j = __ffs(m) - 1;
                m &= m - 1;
                const int gg = __shfl_sync(0xffffffffu, myg, j);
                const long p = (long)(t0 + base + j);
                // row layout: point p -> 64 float4 (view0: +0..31, view1: +32..63)
                const float4 va = X4[p * 64 + lane];
                const float4 vb = X4[p * 64 + 32 + lane];
                const float4 s = make_float4(va.x + vb.x, va.y + vb.y,
                                             va.z + vb.z, va.w + vb.w);
                const int gl = gg & 3;  // warp-uniform
                if (gl == 0)      { a0.x += s.x; a0.y += s.y; a0.z += s.z; a0.w += s.w; n0++; }
                else if (gl == 1) { a1.x += s.x; a1.y += s.y; a1.z += s.z; a1.w += s.w; n1++; }
                else if (gl == 2) { a2.x += s.x; a2.y += s.y; a2.z += s.z; a2.w += s.w; n2++; }
                else              { a3.x += s.x; a3.y += s.y; a3.z += s.z; a3.w += s.w; n3++; }
            }
        }
    }

    // deterministic partial write: this warp fully owns groups 4w..4w+3
    float4* P4 = reinterpret_cast<float4*>(g_part) + (long)blockIdx.x * (G * D / 4);
    P4[(w * 4 + 0) * 32 + lane] = a0;
    P4[(w * 4 + 1) * 32 + lane] = a1;
    P4[(w * 4 + 2) * 32 + lane] = a2;
    P4[(w * 4 + 3) * 32 + lane] = a3;
    if (lane == 0) {
        int* C = g_cntpart + blockIdx.x * G + w * 4;
        C[0] = n0; C[1] = n1; C[2] = n2; C[3] = n3;
    }
}

// ---------------------------------------------------------------------------
// K2: reduce partials -> centroid, counts; zero denssum.
// ---------------------------------------------------------------------------
__global__ __launch_bounds__(256)
void k2_finalize_centroid()
{
    const int t = blockIdx.x * blockDim.x + threadIdx.x;  // 0..16383
    float s = 0.f;
    #pragma unroll 4
    for (int b = 0; b < NB1; b++) s += g_part[b * (G * D) + t];

    const int g = t >> 7;
    int c = 0;
    #pragma unroll 4
    for (int b = 0; b < NB1; b++) c += g_cntpart[b * G + g];
    const float rows = 2.0f * (float)c;

    g_centroid[t] = s / rows;
    if ((t & 127) == 0) g_rows[g] = rows;
    if (t < G) g_denssum[t] = 0.f;
}

// ---------------------------------------------------------------------------
// K3: per-row distance pass. One warp per point (both views, 1024B contig).
// ---------------------------------------------------------------------------
__global__ __launch_bounds__(256)
void k3_density(const float4* __restrict__ X4,
                const int* __restrict__ subj,
                const int* __restrict__ lab,
                int B)
{
    __shared__ float sdens[G];
    if ((int)threadIdx.x < G) sdens[threadIdx.x] = 0.f;
    __syncthreads();

    const int lane = threadIdx.x & 31;
    const int wid  = (blockIdx.x * blockDim.x + threadIdx.x) >> 5;
    const int nw   = (gridDim.x * blockDim.x) >> 5;
    const float4* C4 = reinterpret_cast<const float4*>(g_centroid);

    for (long p = wid; p < B; p += nw) {
        const int g = subj[p] * 8 + lab[p];
        const float4 c  = C4[g * 32 + lane];
        const float4 va = X4[p * 64 + lane];
        const float4 vb = X4[p * 64 + 32 + lane];

        float dx = va.x - c.x, dy = va.y - c.y, dz = va.z - c.z, dw = va.w - c.w;
        float s0 = fmaf(dx, dx, fmaf(dy, dy, fmaf(dz, dz, dw * dw)));
        dx = vb.x - c.x; dy = vb.y - c.y; dz = vb.z - c.z; dw = vb.w - c.w;
        float s1 = fmaf(dx, dx, fmaf(dy, dy, fmaf(dz, dz, dw * dw)));

        #pragma unroll
        for (int o = 16; o > 0; o >>= 1) {
            s0 += __shfl_xor_sync(0xffffffffu, s0, o);
            s1 += __shfl_xor_sync(0xffffffffu, s1, o);
        }
        if (lane == 0) {
            // sqrt(norm) = (ssq)^(1/4)
            const float v = sqrtf(sqrtf(s0)) + sqrtf(sqrtf(s1));
            atomicAdd(&sdens[g], v);
        }
    }
    __syncthreads();
    if ((int)threadIdx.x < G) atomicAdd(&g_denssum[threadIdx.x], sdens[threadIdx.x]);
}

// ---------------------------------------------------------------------------
// K4: scalar epilogue (exact sort via rank for percentile interp).
// ---------------------------------------------------------------------------
__global__ __launch_bounds__(128)
void k4_final(float* __restrict__ out)
{
    __shared__ float dsh[G], sorted[G], coc[G], red[G];
    const int t = threadIdx.x;

    const float rows = g_rows[t];
    const float raw  = (g_denssum[t] / rows) / logf(rows + 10.0f);
    float dz = (rows > 1.0f) ? raw : 0.0f;
    dsh[t] = dz;
    __syncthreads();

    float dmax = -1e30f;
    for (int j = 0; j < G; j++) dmax = fmaxf(dmax, dsh[j]);
    const float dv = (rows > 1.0f) ? dz : dmax;
    __syncthreads();
    dsh[t] = dv;
    __syncthreads();

    // stable rank -> exact sorted order
    int rank = 0;
    for (int j = 0; j < G; j++) {
        const float v = dsh[j];
        rank += (v < dv) || (v == dv && j < t);
    }
    sorted[rank] = dv;
    __syncthreads();

    // percentile(10) at pos 12.7, percentile(90) at pos 114.3 (linear interp)
    const float lo = sorted[12]  + 0.7f * (sorted[13]  - sorted[12]);
    const float hi = sorted[114] + 0.3f * (sorted[115] - sorted[114]);
    const float dc = fminf(fmaxf(dv, lo), hi);

    red[t] = dc;
    __syncthreads();
    float dsum = 0.f;
    for (int j = 0; j < G; j++) dsum += red[j];
    const float dens = 0.1f * dc / (dsum / (float)G);

    // centroid-of-centroids (thread t = dim t)
    float cs = 0.f;
    for (int g = 0; g < G; g++) cs += g_centroid[g * D + t];
    coc[t] = cs / (float)G;
    __syncthreads();

    // dot of this group's centroid with coc
    float dot = 0.f;
    for (int dd = 0; dd < D; dd++) dot += g_centroid[t * D + dd] * coc[dd];
    const float sim = expf(dot / dens);

    red[t] = sim;
    __syncthreads();
    float smax = -1e30f, ssum = 0.f;
    for (int j = 0; j < G; j++) { smax = fmaxf(smax, red[j]); ssum += red[j]; }
    if (t == 0) out[0] = smax - ssum / (float)G;   // -mean(sim - max)
}

// ---------------------------------------------------------------------------
extern "C" void kernel_launch(void* const* d_in, const int* in_sizes, int n_in,
                              void* d_out, int out_size)
{
    const float4* X4  = (const float4*)d_in[0];
    const int* subj   = (const int*)d_in[1];
    const int* lab    = (const int*)d_in[2];
    float* out        = (float*)d_out;
    const int B       = in_sizes[1];   // number of points (subject count)

    k1_centroid_partials<<<NB1, 1024>>>(X4, subj, lab, B);
    k2_finalize_centroid<<<(G * D) / 256, 256>>>();
    k3_density<<<592, 256>>>(X4, subj, lab, B);
    k4_final<<<1, 128>>>(out);
}

// round 4
// speedup vs baseline: 1.1564x; 1.1564x over previous
#include <cuda_runtime.h>

#define NB1 148           // K1 blocks (one wave of 1024-thread blocks); 148 = 4*37
#define G 128             // N_SUBJECTS * N_LABELS
#define D 128

// Scratch (no allocations allowed): ~9.8 MB
__device__ float g_part[NB1 * G * D];     // per-block partial centroid sums
__device__ int   g_cntpart[NB1 * G];      // per-block partial point counts
__device__ float g_centroid[G * D];
__device__ float g_rows[G];               // row counts (2 * point count), as float
__device__ float g_denssum[G];
__device__ float g_dot[G];                // centroid[g] . coc

// ---------------------------------------------------------------------------
// K1: per-block partial segment sums. Each warp owns 4 groups, accumulates in
// registers; membership via ballot scan of staged group ids. No fp atomics.
// ---------------------------------------------------------------------------
__global__ __launch_bounds__(1024, 1)
void k1_centroid_partials(const float4* __restrict__ X4,
                          const int* __restrict__ subj,
                          const int* __restrict__ lab,
                          int B)
{
    __shared__ int sg[1024];
    const int w    = threadIdx.x >> 5;     // warp id 0..31, owns groups [4w,4w+4)
    const int lane = threadIdx.x & 31;

    const int chunk = (B + gridDim.x - 1) / gridDim.x;
    const int c0 = blockIdx.x * chunk;
    const int c1 = min(c0 + chunk, B);

    float4 a0 = make_float4(0.f,0.f,0.f,0.f);
    float4 a1 = a0, a2 = a0, a3 = a0;
    int n0 = 0, n1 = 0, n2 = 0, n3 = 0;

    for (int t0 = c0; t0 < c1; t0 += 1024) {
        const int n = min(1024, c1 - t0);
        __syncthreads();
        if ((int)threadIdx.x < n) {
            int p = t0 + threadIdx.x;
            sg[threadIdx.x] = subj[p] * 8 + lab[p];
        }
        __syncthreads();

        for (int base = 0; base < n; base += 32) {
            const int i = base + lane;
            const int myg = (i < n) ? sg[i] : -1;
            unsigned m = __ballot_sync(0xffffffffu, (myg >> 2) == w);
            while (m) {
                const int j = __ffs(m) - 1;
                m &= m - 1;
                const int gg = __shfl_sync(0xffffffffu, myg, j);
                const long p = (long)(t0 + base + j);
                // row layout: point p -> 64 float4 (view0: +0..31, view1: +32..63)
                const float4 va = X4[p * 64 + lane];
                const float4 vb = X4[p * 64 + 32 + lane];
                const float4 s = make_float4(va.x + vb.x, va.y + vb.y,
                                             va.z + vb.z, va.w + vb.w);
                const int gl = gg & 3;  // warp-uniform
                if (gl == 0)      { a0.x += s.x; a0.y += s.y; a0.z += s.z; a0.w += s.w; n0++; }
                else if (gl == 1) { a1.x += s.x; a1.y += s.y; a1.z += s.z; a1.w += s.w; n1++; }
                else if (gl == 2) { a2.x += s.x; a2.y += s.y; a2.z += s.z; a2.w += s.w; n2++; }
                else              { a3.x += s.x; a3.y += s.y; a3.z += s.z; a3.w += s.w; n3++; }
            }
        }
    }

    // deterministic partial write: this warp fully owns groups 4w..4w+3
    float4* P4 = reinterpret_cast<float4*>(g_part) + (long)blockIdx.x * (G * D / 4);
    P4[(w * 4 + 0) * 32 + lane] = a0;
    P4[(w * 4 + 1) * 32 + lane] = a1;
    P4[(w * 4 + 2) * 32 + lane] = a2;
    P4[(w * 4 + 3) * 32 + lane] = a3;
    if (lane == 0) {
        int* C = g_cntpart + blockIdx.x * G + w * 4;
        C[0] = n0; C[1] = n1; C[2] = n2; C[3] = n3;
    }
}

// ---------------------------------------------------------------------------
// K2: reduce partials -> centroid, counts. One block per group, 512 threads:
// thread = (slice 0..3, dim 0..127), 37 fully-unrolled independent loads each.
// ---------------------------------------------------------------------------
__global__ __launch_bounds__(512)
void k2_finalize_centroid()
{
    __shared__ float red[512];
    __shared__ int   scnt[256];
    const int g     = blockIdx.x;
    const int tid   = threadIdx.x;
    const int d     = tid & 127;
    const int slice = tid >> 7;            // 0..3, each covers 37 of 148 blocks

    const float* base = g_part + g * D + d;
    float s = 0.f;
    const int b0 = slice * 37;
    #pragma unroll
    for (int i = 0; i < 37; i++) s += base[(long)(b0 + i) * (G * D)];
    red[tid] = s;

    // counts: 148 partials, parallel tree reduce
    if (tid < 256) {
        int c = 0;
        for (int b = tid; b < NB1; b += 256) c += g_cntpart[b * G + g];
        scnt[tid] = c;
    }
    __syncthreads();
    #pragma unroll
    for (int o = 128; o >= 1; o >>= 1) {
        if (tid < o) scnt[tid] += scnt[tid + o];
        __syncthreads();
    }
    const float rows = 2.0f * (float)scnt[0];

    if (slice == 0) {
        const float tot = red[d] + red[d + 128] + red[d + 256] + red[d + 384];
        g_centroid[g * D + d] = tot / rows;
    }
    if (tid == 0) { g_rows[g] = rows; g_denssum[g] = 0.f; }
}

// ---------------------------------------------------------------------------
// K2b: coc = mean centroid, then dot[g] = centroid[g] . coc. 1 block, L2-hot.
// ---------------------------------------------------------------------------
__global__ __launch_bounds__(1024, 1)
void k2b_coc_dots()
{
    __shared__ float part[1024];
    __shared__ float4 coc4[32];
    const int tid   = threadIdx.x;
    const int d     = tid & 127;
    const int slice = tid >> 7;            // 0..7, each covers 16 groups

    float s = 0.f;
    #pragma unroll
    for (int i = 0; i < 16; i++) s += g_centroid[(slice * 16 + i) * D + d];
    part[tid] = s;
    __syncthreads();
    if (tid < 128) {
        float t = 0.f;
        #pragma unroll
        for (int j = 0; j < 8; j++) t += part[j * 128 + tid];
        reinterpret_cast<float*>(coc4)[tid] = t * (1.0f / (float)G);
    }
    __syncthreads();

    // one warp per 4 groups: dot product via butterfly
    const int w    = tid >> 5;             // 0..31
    const int lane = tid & 31;
    const float4* C4 = reinterpret_cast<const float4*>(g_centroid);
    #pragma unroll
    for (int k = 0; k < 4; k++) {
        const int gg = w * 4 + k;
        const float4 c = C4[gg * 32 + lane];
        const float4 o = coc4[lane];
        float dot = fmaf(c.x, o.x, fmaf(c.y, o.y, fmaf(c.z, o.z, c.w * o.w)));
        #pragma unroll
        for (int off = 16; off > 0; off >>= 1)
            dot += __shfl_xor_sync(0xffffffffu, dot, off);
        if (lane == 0) g_dot[gg] = dot;
    }
}

// ---------------------------------------------------------------------------
// K3: per-row distance pass. One warp per point (both views, 1024B contig).
// ---------------------------------------------------------------------------
__global__ __launch_bounds__(256)
void k3_density(const float4* __restrict__ X4,
                const int* __restrict__ subj,
                const int* __restrict__ lab,
                int B)
{
    __shared__ float sdens[G];
    if ((int)threadIdx.x < G) sdens[threadIdx.x] = 0.f;
    __syncthreads();

    const int lane = threadIdx.x & 31;
    const int wid  = (blockIdx.x * blockDim.x + threadIdx.x) >> 5;
    const int nw   = (gridDim.x * blockDim.x) >> 5;
    const float4* C4 = reinterpret_cast<const float4*>(g_centroid);

    for (long p = wid; p < B; p += nw) {
        const int g = subj[p] * 8 + lab[p];
        const float4 c  = C4[g * 32 + lane];
        const float4 va = X4[p * 64 + lane];
        const float4 vb = X4[p * 64 + 32 + lane];

        float dx = va.x - c.x, dy = va.y - c.y, dz = va.z - c.z, dw = va.w - c.w;
        float s0 = fmaf(dx, dx, fmaf(dy, dy, fmaf(dz, dz, dw * dw)));
        dx = vb.x - c.x; dy = vb.y - c.y; dz = vb.z - c.z; dw = vb.w - c.w;
        float s1 = fmaf(dx, dx, fmaf(dy, dy, fmaf(dz, dz, dw * dw)));

        #pragma unroll
        for (int o = 16; o > 0; o >>= 1) {
            s0 += __shfl_xor_sync(0xffffffffu, s0, o);
            s1 += __shfl_xor_sync(0xffffffffu, s1, o);
        }
        if (lane == 0) {
            // sqrt(norm) = (ssq)^(1/4)
            const float v = sqrtf(sqrtf(s0)) + sqrtf(sqrtf(s1));
            atomicAdd(&sdens[g], v);
        }
    }
    __syncthreads();
    if ((int)threadIdx.x < G) atomicAdd(&g_denssum[threadIdx.x], sdens[threadIdx.x]);
}

// ---------------------------------------------------------------------------
// K4: scalar epilogue, O(G) shared-memory work only (dots precomputed in k2b).
// ---------------------------------------------------------------------------
__global__ __launch_bounds__(128)
void k4_final(float* __restrict__ out)
{
    __shared__ float dsh[G], sorted[G], red[G];
    const int t = threadIdx.x;

    const float rows = g_rows[t];
    const float raw  = (g_denssum[t] / rows) / logf(rows + 10.0f);
    float dz = (rows > 1.0f) ? raw : 0.0f;
    dsh[t] = dz;
    __syncthreads();

    float dmax = -1e30f;
    #pragma unroll 8
    for (int j = 0; j < G; j++) dmax = fmaxf(dmax, dsh[j]);
    const float dv = (rows > 1.0f) ? dz : dmax;
    __syncthreads();
    dsh[t] = dv;
    __syncthreads();

    // stable rank -> exact sorted order
    int rank = 0;
    #pragma unroll 8
    for (int j = 0; j < G; j++) {
        const float v = dsh[j];
        rank += (v < dv) || (v == dv && j < t);
    }
    sorted[rank] = dv;
    __syncthreads();

    // percentile(10) at pos 12.7, percentile(90) at pos 114.3 (linear interp)
    const float lo = sorted[12]  + 0.7f * (sorted[13]  - sorted[12]);
    const float hi = sorted[114] + 0.3f * (sorted[115] - sorted[114]);
    const float dc = fminf(fmaxf(dv, lo), hi);

    red[t] = dc;
    __syncthreads();
    float dsum = 0.f;
    #pragma unroll 8
    for (int j = 0; j < G; j++) dsum += red[j];
    const float dens = 0.1f * dc / (dsum / (float)G);

    const float sim = expf(g_dot[t] / dens);

    red[t] = sim;
    __syncthreads();
    float smax = -1e30f, ssum = 0.f;
    #pragma unroll 8
    for (int j = 0; j < G; j++) { smax = fmaxf(smax, red[j]); ssum += red[j]; }
    if (t == 0) out[0] = smax - ssum / (float)G;   // -mean(sim - max)
}

// ---------------------------------------------------------------------------
extern "C" void kernel_launch(void* const* d_in, const int* in_sizes, int n_in,
                              void* d_out, int out_size)
{
    const float4* X4  = (const float4*)d_in[0];
    const int* subj   = (const int*)d_in[1];
    const int* lab    = (const int*)d_in[2];
    float* out        = (float*)d_out;
    const int B       = in_sizes[1];   // number of points (subject count)

    k1_centroid_partials<<<NB1, 1024>>>(X4, subj, lab, B);
    k2_finalize_centroid<<<G, 512>>>();
    k2b_coc_dots<<<1, 1024>>>();
    k3_density<<<1184, 256>>>(X4, subj, lab, B);
    k4_final<<<1, 128>>>(out);
}

// round 5
// speedup vs baseline: 1.6609x; 1.4363x over previous
#include <cuda_runtime.h>

#define NB1 148           // K1 blocks (one full wave of 1024-thread blocks)
#define G 128             // N_SUBJECTS * N_LABELS
#define D 128
#define T1 64             // K1 tile size (points)
#define BMAX (1 << 17)    // 131072 points

// Scratch (no allocations allowed): ~10.3 MB
__device__ float g_part[NB1 * G * D];     // per-block partial centroid sums
__device__ int   g_cntpart[NB1 * G];      // per-block partial point counts
__device__ float g_centroid[G * D];
__device__ float g_rows[G];               // row counts (2 * point count), as float
__device__ float g_denssum[G];
__device__ float g_dot[G];                // centroid[g] . coc
__device__ int   g_gid[BMAX];             // combined group id per point

// ---------------------------------------------------------------------------
// K1: pipelined tile staging. All threads stream a 64-point tile with
// parallel coalesced LDG (views combined in regs), stage it in shared, then
// owner-warps (4 groups each) accumulate from shared via ballot scan.
// Next tile's global loads are issued before the shared scan -> overlap.
// ---------------------------------------------------------------------------
__global__ __launch_bounds__(1024, 1)
void k1_centroid_partials(const float4* __restrict__ X4,
                          const int* __restrict__ subj,
                          const int* __restrict__ lab,
                          int B)
{
    __shared__ float4 sbuf[T1 * 32];      // 64 pts x 128 floats (combined views)
    __shared__ int    sg[T1];

    const int tid  = threadIdx.x;
    const int w    = tid >> 5;            // warp 0..31 owns groups [4w, 4w+4)
    const int lane = tid & 31;
    const int j    = tid >> 4;            // stage-A point within tile (0..63)
    const int k    = (tid & 15) << 1;     // stage-A float4-pair index (0..30)

    const int chunk = (B + gridDim.x - 1) / gridDim.x;
    const int c0 = blockIdx.x * chunk;
    const int c1 = min(c0 + chunk, B);

    float4 a0 = make_float4(0.f, 0.f, 0.f, 0.f);
    float4 a1 = a0, a2 = a0, a3 = a0;
    int n0 = 0, n1 = 0, n2 = 0, n3 = 0;

    float4 r0, r1, r2, r3;                // prefetch registers
    int pg = -1;

    // prologue: prefetch tile 0
    {
        const int p = c0 + j;
        if (p < c1) {
            const float4* Xp = X4 + (size_t)p * 64;
            r0 = Xp[k]; r1 = Xp[k + 1]; r2 = Xp[32 + k]; r3 = Xp[33 + k];
        } else {
            r0 = r1 = r2 = r3 = make_float4(0.f, 0.f, 0.f, 0.f);
        }
        if (tid < T1) {
            const int pp = c0 + tid;
            pg = (pp < c1) ? subj[pp] * 8 + lab[pp] : -1;
        }
    }

    for (int t0 = c0; t0 < c1; t0 += T1) {
        // stage A commit: combined views -> shared
        sbuf[j * 32 + k]     = make_float4(r0.x + r2.x, r0.y + r2.y,
                                           r0.z + r2.z, r0.w + r2.w);
        sbuf[j * 32 + k + 1] = make_float4(r1.x + r3.x, r1.y + r3.y,
                                           r1.z + r3.z, r1.w + r3.w);
        if (tid < T1) {
            sg[tid] = pg;
            if (t0 + tid < c1) g_gid[t0 + tid] = pg;
        }
        __syncthreads();

        // prefetch next tile (overlaps with the shared scan below)
        const int tn = t0 + T1;
        if (tn < c1) {
            const int p = tn + j;
            if (p < c1) {
                const float4* Xp = X4 + (size_t)p * 64;
                r0 = Xp[k]; r1 = Xp[k + 1]; r2 = Xp[32 + k]; r3 = Xp[33 + k];
            } else {
                r0 = r1 = r2 = r3 = make_float4(0.f, 0.f, 0.f, 0.f);
            }
            if (tid < T1) {
                const int pp = tn + tid;
                pg = (pp < c1) ? subj[pp] * 8 + lab[pp] : -1;
            }
        }

        // stage B: ballot scan over staged tile (shared only)
        #pragma unroll
        for (int base = 0; base < T1; base += 32) {
            const int myg = sg[base + lane];          // -1 for padding: never matches
            unsigned m = __ballot_sync(0xffffffffu, (myg >> 2) == w);
            while (m) {
                const int jj = __ffs(m) - 1;
                m &= m - 1;
                const int gg = __shfl_sync(0xffffffffu, myg, jj);
                const float4 s = sbuf[(base + jj) * 32 + lane];
                const int gl = gg & 3;                // warp-uniform
                if (gl == 0)      { a0.x += s.x; a0.y += s.y; a0.z += s.z; a0.w += s.w; n0++; }
                else if (gl == 1) { a1.x += s.x; a1.y += s.y; a1.z += s.z; a1.w += s.w; n1++; }
                else if (gl == 2) { a2.x += s.x; a2.y += s.y; a2.z += s.z; a2.w += s.w; n2++; }
                else              { a3.x += s.x; a3.y += s.y; a3.z += s.z; a3.w += s.w; n3++; }
            }
        }
        __syncthreads();
    }

    // deterministic partial write: this warp fully owns groups 4w..4w+3
    float4* P4 = reinterpret_cast<float4*>(g_part) + (long)blockIdx.x * (G * D / 4);
    P4[(w * 4 + 0) * 32 + lane] = a0;
    P4[(w * 4 + 1) * 32 + lane] = a1;
    P4[(w * 4 + 2) * 32 + lane] = a2;
    P4[(w * 4 + 3) * 32 + lane] = a3;
    if (lane == 0) {
        int* C = g_cntpart + blockIdx.x * G + w * 4;
        C[0] = n0; C[1] = n1; C[2] = n2; C[3] = n3;
    }
}

// ---------------------------------------------------------------------------
// K2: reduce partials -> centroid, counts. One block per group, 512 threads:
// thread = (slice 0..3, dim 0..127), 37 fully-unrolled independent loads each.
// ---------------------------------------------------------------------------
__global__ __launch_bounds__(512)
void k2_finalize_centroid()
{
    __shared__ float red[512];
    __shared__ int   scnt[256];
    const int g     = blockIdx.x;
    const int tid   = threadIdx.x;
    const int d     = tid & 127;
    const int slice = tid >> 7;            // 0..3, each covers 37 of 148 blocks

    const float* base = g_part + g * D + d;
    float s = 0.f;
    const int b0 = slice * 37;
    #pragma unroll
    for (int i = 0; i < 37; i++) s += base[(long)(b0 + i) * (G * D)];
    red[tid] = s;

    if (tid < 256) {
        int c = 0;
        for (int b = tid; b < NB1; b += 256) c += g_cntpart[b * G + g];
        scnt[tid] = c;
    }
    __syncthreads();
    #pragma unroll
    for (int o = 128; o >= 1; o >>= 1) {
        if (tid < o) scnt[tid] += scnt[tid + o];
        __syncthreads();
    }
    const float rows = 2.0f * (float)scnt[0];

    if (slice == 0) {
        const float tot = red[d] + red[d + 128] + red[d + 256] + red[d + 384];
        g_centroid[g * D + d] = tot / rows;
    }
    if (tid == 0) { g_rows[g] = rows; g_denssum[g] = 0.f; }
}

// ---------------------------------------------------------------------------
// K2b: coc = mean centroid, then dot[g] = centroid[g] . coc. 1 block, L2-hot.
// ---------------------------------------------------------------------------
__global__ __launch_bounds__(1024, 1)
void k2b_coc_dots()
{
    __shared__ float part[1024];
    __shared__ float4 coc4[32];
    const int tid   = threadIdx.x;
    const int d     = tid & 127;
    const int slice = tid >> 7;            // 0..7, each covers 16 groups

    float s = 0.f;
    #pragma unroll
    for (int i = 0; i < 16; i++) s += g_centroid[(slice * 16 + i) * D + d];
    part[tid] = s;
    __syncthreads();
    if (tid < 128) {
        float t = 0.f;
        #pragma unroll
        for (int j = 0; j < 8; j++) t += part[j * 128 + tid];
        reinterpret_cast<float*>(coc4)[tid] = t * (1.0f / (float)G);
    }
    __syncthreads();

    const int w    = tid >> 5;             // 0..31, one warp per 4 groups
    const int lane = tid & 31;
    const float4* C4 = reinterpret_cast<const float4*>(g_centroid);
    #pragma unroll
    for (int kk = 0; kk < 4; kk++) {
        const int gg = w * 4 + kk;
        const float4 c = C4[gg * 32 + lane];
        const float4 o = coc4[lane];
        float dot = fmaf(c.x, o.x, fmaf(c.y, o.y, fmaf(c.z, o.z, c.w * o.w)));
        #pragma unroll
        for (int off = 16; off > 0; off >>= 1)
            dot += __shfl_xor_sync(0xffffffffu, dot, off);
        if (lane == 0) g_dot[gg] = dot;
    }
}

// ---------------------------------------------------------------------------
// K3: per-row distance pass. One warp per point; merged dual-value butterfly
// (7 shuffles for both views); 2-point manual unroll for MLP.
// ---------------------------------------------------------------------------
__device__ __forceinline__ float k3_point(const float4* __restrict__ X4,
                                          const float4* __restrict__ C4,
                                          const int* __restrict__ gid,
                                          int p, int lane, int* gout)
{
    const int g = gid[p];                  // warp-uniform broadcast load
    *gout = g;
    const float4 c  = C4[g * 32 + lane];
    const float4 va = X4[p * 64 + lane];
    const float4 vb = X4[p * 64 + 32 + lane];

    float dx = va.x - c.x, dy = va.y - c.y, dz = va.z - c.z, dw = va.w - c.w;
    float s0 = fmaf(dx, dx, fmaf(dy, dy, fmaf(dz, dz, dw * dw)));
    dx = vb.x - c.x; dy = vb.y - c.y; dz = vb.z - c.z; dw = vb.w - c.w;
    float s1 = fmaf(dx, dx, fmaf(dy, dy, fmaf(dz, dz, dw * dw)));

    // merged reduction: lanes 0..15 reduce s0, lanes 16..31 reduce s1
    const float s0x = __shfl_xor_sync(0xffffffffu, s0, 16);
    const float s1x = __shfl_xor_sync(0xffffffffu, s1, 16);
    float m = (lane & 16) ? (s1 + s1x) : (s0 + s0x);
    #pragma unroll
    for (int o = 8; o > 0; o >>= 1)
        m += __shfl_xor_sync(0xffffffffu, m, o);
    // lane 0 holds sum(s0), lane 16 holds sum(s1)
    const float q  = sqrtf(sqrtf(m));      // (ssq)^(1/4)
    const float qx = __shfl_xor_sync(0xffffffffu, q, 16);
    return q + qx;                         // valid on lane 0
}

__global__ __launch_bounds__(256)
void k3_density(const float4* __restrict__ X4,
                const int* __restrict__ gid,
                int B)
{
    __shared__ float sdens[G];
    if ((int)threadIdx.x < G) sdens[threadIdx.x] = 0.f;
    __syncthreads();

    const int lane = threadIdx.x & 31;
    const int wid  = (blockIdx.x * blockDim.x + threadIdx.x) >> 5;
    const int nw   = (gridDim.x * blockDim.x) >> 5;
    const float4* C4 = reinterpret_cast<const float4*>(g_centroid);

    int p = wid;
    for (; p + nw < B; p += 2 * nw) {      // 2 independent points in flight
        int ga, gb;
        const float va = k3_point(X4, C4, gid, p,      lane, &ga);
        const float vb = k3_point(X4, C4, gid, p + nw, lane, &gb);
        if (lane == 0) {
            atomicAdd(&sdens[ga], va);
            atomicAdd(&sdens[gb], vb);
        }
    }
    if (p < B) {
        int ga;
        const float va = k3_point(X4, C4, gid, p, lane, &ga);
        if (lane == 0) atomicAdd(&sdens[ga], va);
    }

    __syncthreads();
    if ((int)threadIdx.x < G) atomicAdd(&g_denssum[threadIdx.x], sdens[threadIdx.x]);
}

// ---------------------------------------------------------------------------
// K4: scalar epilogue, O(G) shared-memory work only (dots precomputed in k2b).
// ---------------------------------------------------------------------------
__global__ __launch_bounds__(128)
void k4_final(float* __restrict__ out)
{
    __shared__ float dsh[G], sorted[G], red[G];
    const int t = threadIdx.x;

    const float rows = g_rows[t];
    const float raw  = (g_denssum[t] / rows) / logf(rows + 10.0f);
    float dz = (rows > 1.0f) ? raw : 0.0f;
    dsh[t] = dz;
    __syncthreads();

    float dmax = -1e30f;
    #pragma unroll 8
    for (int j = 0; j < G; j++) dmax = fmaxf(dmax, dsh[j]);
    const float dv = (rows > 1.0f) ? dz : dmax;
    __syncthreads();
    dsh[t] = dv;
    __syncthreads();

    // stable rank -> exact sorted order
    int rank = 0;
    #pragma unroll 8
    for (int j = 0; j < G; j++) {
        const float v = dsh[j];
        rank += (v < dv) || (v == dv && j < t);
    }
    sorted[rank] = dv;
    __syncthreads();

    // percentile(10) at pos 12.7, percentile(90) at pos 114.3 (linear interp)
    const float lo = sorted[12]  + 0.7f * (sorted[13]  - sorted[12]);
    const float hi = sorted[114] + 0.3f * (sorted[115] - sorted[114]);
    const float dc = fminf(fmaxf(dv, lo), hi);

    red[t] = dc;
    __syncthreads();
    float dsum = 0.f;
    #pragma unroll 8
    for (int j = 0; j < G; j++) dsum += red[j];
    const float dens = 0.1f * dc / (dsum / (float)G);

    const float sim = expf(g_dot[t] / dens);

    red[t] = sim;
    __syncthreads();
    float smax = -1e30f, ssum = 0.f;
    #pragma unroll 8
    for (int j = 0; j < G; j++) { smax = fmaxf(smax, red[j]); ssum += red[j]; }
    if (t == 0) out[0] = smax - ssum / (float)G;   // -mean(sim - max)
}

// ---------------------------------------------------------------------------
extern "C" void kernel_launch(void* const* d_in, const int* in_sizes, int n_in,
                              void* d_out, int out_size)
{
    const float4* X4  = (const float4*)d_in[0];
    const int* subj   = (const int*)d_in[1];
    const int* lab    = (const int*)d_in[2];
    float* out        = (float*)d_out;
    const int B       = in_sizes[1];   // number of points

    int* gid;
    cudaGetSymbolAddress((void**)&gid, g_gid);

    k1_centroid_partials<<<NB1, 1024>>>(X4, subj, lab, B);
    k2_finalize_centroid<<<G, 512>>>();
    k2b_coc_dots<<<1, 1024>>>();
    k3_density<<<1184, 256>>>(X4, gid, B);
    k4_final<<<1, 128>>>(out);
}